// round 5
// baseline (speedup 1.0000x reference)
#include <cuda_runtime.h>
#include <cstdint>
#include <cstddef>

#define BB 4
#define NN 16384
#define NPT 1024
#define NS 32
#define CF 64
#define CIN 67
#define CL 4  // CTAs per cluster (one cluster per batch)

// scratch: neighbor indices (B, NPOINT, NSAMPLE)
__device__ int g_nidx[BB * NPT * NS];

// ---- packed f32x2 helpers (per-lane IEEE rn, identical to scalar __fadd_rn/__fmul_rn)
typedef unsigned long long u64;
__device__ __forceinline__ u64 f2_add(u64 a, u64 b) {
    u64 r;
    asm("add.rn.f32x2 %0, %1, %2;" : "=l"(r) : "l"(a), "l"(b));
    return r;
}
__device__ __forceinline__ u64 f2_mul(u64 a, u64 b) {
    u64 r;
    asm("mul.rn.f32x2 %0, %1, %2;" : "=l"(r) : "l"(a), "l"(b));
    return r;
}
__device__ __forceinline__ u64 f2_pack(float lo, float hi) {
    u64 r;
    asm("mov.b64 %0, {%1, %2};" : "=l"(r) : "f"(lo), "f"(hi));
    return r;
}
__device__ __forceinline__ float2 f2_unpack(u64 v) {
    float2 r;
    asm("mov.b64 {%0, %1}, %2;" : "=f"(r.x), "=f"(r.y) : "l"(v));
    return r;
}
__device__ __forceinline__ u64 umax64(u64 a, u64 b) { return a > b ? a : b; }
__device__ __forceinline__ uint32_t redux_max(uint32_t v) {
    uint32_t r;
    asm("redux.sync.max.u32 %0, %1, 0xffffffff;" : "=r"(r) : "r"(v));
    return r;
}
__device__ __forceinline__ uint32_t smem_u32(const void* p) {
    return (uint32_t)__cvta_generic_to_shared(p);
}
__device__ __forceinline__ void st_cluster_u64(uint32_t laddr, uint32_t rank, u64 v) {
    uint32_t r;
    asm volatile("mapa.shared::cluster.u32 %0, %1, %2;" : "=r"(r) : "r"(laddr), "r"(rank));
    asm volatile("st.relaxed.cluster.shared::cluster.u64 [%0], %1;" ::"r"(r), "l"(v)
                 : "memory");
}
__device__ __forceinline__ u64 ld_mbox(uint32_t laddr) {
    u64 v;
    asm volatile("ld.relaxed.cluster.shared::cta.u64 %0, [%1];" : "=l"(v) : "r"(laddr)
                 : "memory");
    return v;
}
__device__ __forceinline__ void cluster_sync_all() {
    asm volatile("barrier.cluster.arrive.aligned;" ::: "memory");
    asm volatile("barrier.cluster.wait.aligned;" ::: "memory");
}

// mailbox word: (p+1)(11b) << 53 | dist_bits(32b) << 21 | negidx(14b)
// Equal tags -> u64 max == (dist, -idx) lexicographic max == jnp.argmax semantics.

// ---------------------------------------------------------------------------
// FPS: 4-CTA cluster per batch. Full packed xyz copy per CTA; each CTA updates
// dists for its 4096 points. NO intra-CTA barrier and NO stage-2 reduction:
// every warp publishes its 32-lane partial directly to all 4 CTAs' mailboxes
// (128 tagged words per CTA), then each warp independently polls all 128
// words and reduces them. Parity double-buffered; tag monotonicity makes the
// scheme WAR-safe and deadlock-free without any barriers in the loop.
// ---------------------------------------------------------------------------
__global__ __launch_bounds__(1024, 1) __cluster_dims__(CL, 1, 1)
void fps_kernel(const float* __restrict__ xyz, float* __restrict__ newxyz) {
    extern __shared__ unsigned char smraw[];
    ulonglong2* A = (ulonglong2*)smraw;            // 8192 x 16B = 128 KB
    u64* Z = (u64*)(smraw + 8192 * 16);            // 8192 x 8B  =  64 KB
    __shared__ u64 mbox[2][CL * 32];               // [parity][rank*32+warp]

    const int b = blockIdx.x / CL;
    const int rank = blockIdx.x % CL;
    const int tid = threadIdx.x;
    const float* base = xyz + (size_t)b * NN * 3;

    // full packed copy (every CTA); slot s packs points (s, s+8192)
    for (int s = tid; s < 8192; s += 1024) {
        const int ia = s, ib = s + 8192;
        ulonglong2 av;
        av.x = f2_pack(base[3 * ia + 0], base[3 * ib + 0]);
        av.y = f2_pack(base[3 * ia + 1], base[3 * ib + 1]);
        A[s] = av;
        Z[s] = f2_pack(base[3 * ia + 2], base[3 * ib + 2]);
    }
    if (tid < 2 * CL * 32) ((u64*)mbox)[tid] = 0;  // tags start at 1; 0 never matches

    const int s0 = rank * 2048 + tid;  // this thread's two packed slots
    const int s1 = s0 + 1024;
    const uint32_t ni0a = (uint32_t)(16383 - s0);
    const uint32_t ni0b = (uint32_t)(16383 - (s0 + 8192));
    const uint32_t ni1a = (uint32_t)(16383 - s1);
    const uint32_t ni1b = (uint32_t)(16383 - (s1 + 8192));

    float2 d20 = make_float2(1e10f, 1e10f);
    float2 d21 = make_float2(1e10f, 1e10f);

    __syncthreads();
    cluster_sync_all();  // tiles + mailboxes initialized cluster-wide from here

    int f = 0;
    float* outp = newxyz + (size_t)b * NPT * 3;
    const int lane = tid & 31, wid = tid >> 5;
    const uint32_t mb0 = smem_u32(&mbox[0][0]);
    // this warp's slot (same offset in every CTA's mailbox)
    const uint32_t myslot_off = (uint32_t)(rank * 32 + wid) * 8u;

    for (int p = 0; p < NPT; ++p) {
        // centroid fetch (local, full copy)
        const int fslot = f & 8191;
        const int fhalf = f >> 13;
        const ulonglong2 fa = A[fslot];
        const float2 fx = f2_unpack(fa.x);
        const float2 fy = f2_unpack(fa.y);
        const float2 fz = f2_unpack(Z[fslot]);
        const float cx = fhalf ? fx.y : fx.x;
        const float cy = fhalf ? fy.y : fy.x;
        const float cz = fhalf ? fz.y : fz.x;
        if (rank == 0 && tid == 0) {
            outp[3 * p + 0] = cx;
            outp[3 * p + 1] = cy;
            outp[3 * p + 2] = cz;
        }
        const u64 ncx = f2_pack(-cx, -cx);
        const u64 ncy = f2_pack(-cy, -cy);
        const u64 ncz = f2_pack(-cz, -cz);

        u64 loc;
        {
            const ulonglong2 av = A[s0];
            const u64 zv = Z[s0];
            const u64 dx = f2_add(av.x, ncx);
            const u64 dy = f2_add(av.y, ncy);
            const u64 dz = f2_add(zv, ncz);
            const float2 d =
                f2_unpack(f2_add(f2_add(f2_mul(dx, dx), f2_mul(dy, dy)), f2_mul(dz, dz)));
            d20.x = fminf(d20.x, d.x);
            d20.y = fminf(d20.y, d.y);
            const u64 k0 = ((u64)__float_as_uint(d20.x) << 21) | ni0a;
            const u64 k1 = ((u64)__float_as_uint(d20.y) << 21) | ni0b;
            loc = umax64(k0, k1);
        }
        {
            const ulonglong2 av = A[s1];
            const u64 zv = Z[s1];
            const u64 dx = f2_add(av.x, ncx);
            const u64 dy = f2_add(av.y, ncy);
            const u64 dz = f2_add(zv, ncz);
            const float2 d =
                f2_unpack(f2_add(f2_add(f2_mul(dx, dx), f2_mul(dy, dy)), f2_mul(dz, dz)));
            d21.x = fminf(d21.x, d.x);
            d21.y = fminf(d21.y, d.y);
            const u64 k0 = ((u64)__float_as_uint(d21.x) << 21) | ni1a;
            const u64 k1 = ((u64)__float_as_uint(d21.y) << 21) | ni1b;
            loc = umax64(loc, umax64(k0, k1));
        }

        // warp argmax via two redux ops
        const uint32_t dbits = (uint32_t)(loc >> 21);
        const uint32_t wmax = redux_max(dbits);
        const uint32_t cand = (dbits == wmax) ? (uint32_t)(loc & 0x3FFFu) : 0u;
        const uint32_t nmax = redux_max(cand);

        const int par = p & 1;
        const uint32_t parbase = (uint32_t)(par * CL * 32) * 8u;
        // lanes 0..3 publish this warp's partial to all 4 ranks (tagged)
        const u64 msg = ((u64)(p + 1) << 53) | ((u64)wmax << 21) | nmax;
        if (lane < CL) st_cluster_u64(mb0 + parbase + myslot_off, (uint32_t)lane, msg);

        // poll all 128 partials: lane l handles words l, l+32, l+64, l+96
        u64 g = 0;
#pragma unroll
        for (int j = 0; j < CL; j++) {
            const uint32_t a = mb0 + parbase + (uint32_t)(lane + j * 32) * 8u;
            u64 v;
            do {
                v = ld_mbox(a);
            } while ((v >> 53) != (u64)(p + 1));
            g = umax64(g, v);
        }
        // warp-wide max of the 128 partials (tags equal -> payload order)
        const uint32_t gd = (uint32_t)(g >> 21);
        const uint32_t gmax = redux_max(gd);
        const uint32_t gcand = (gd == gmax) ? (uint32_t)(g & 0x3FFFu) : 0u;
        const uint32_t gn = redux_max(gcand);
        f = 16383 - (int)gn;
    }
    cluster_sync_all();  // no CTA exits while peers may still store into it
}

// ---------------------------------------------------------------------------
// Ball query: one warp per centroid. Scan points in index order, append the
// first 32 within radius (strict d2 < 0.01f), pad with the first hit.
// ---------------------------------------------------------------------------
__global__ __launch_bounds__(256) void ball_kernel(const float* __restrict__ xyz,
                                                   const float* __restrict__ newxyz) {
    const int gw = (int)((blockIdx.x * blockDim.x + threadIdx.x) >> 5);
    const int lane = threadIdx.x & 31;
    if (gw >= BB * NPT) return;
    const int b = gw >> 10;

    const float* nx = newxyz + (size_t)gw * 3;
    const float cx = nx[0], cy = nx[1], cz = nx[2];
    const float* px = xyz + (size_t)b * NN * 3;
    int* out = g_nidx + (size_t)gw * NS;

    int count = 0;
    int first = 0;
    bool havefirst = false;

    for (int bs = 0; bs < NN; bs += 32) {
        const int i = bs + lane;
        const float dx = __fadd_rn(px[3 * i + 0], -cx);
        const float dy = __fadd_rn(px[3 * i + 1], -cy);
        const float dz = __fadd_rn(px[3 * i + 2], -cz);
        const float d2 =
            __fadd_rn(__fadd_rn(__fmul_rn(dx, dx), __fmul_rn(dy, dy)), __fmul_rn(dz, dz));
        const bool win = d2 < 0.01f;
        const unsigned m = __ballot_sync(0xffffffffu, win);
        if (m) {
            if (!havefirst) {
                first = bs + __ffs(m) - 1;
                havefirst = true;
            }
            const int slot = count + __popc(m & ((1u << lane) - 1u));
            if (win && slot < NS) out[slot] = i;
            count += __popc(m);
            if (count >= NS) break;
        }
    }
    if (lane >= count) out[lane] = first;  // pad (count<32 case); no-op if count>=32
}

// ---------------------------------------------------------------------------
// Gather + 3-layer MLP + max-pool. One warp per centroid, lane = sample.
// Weights in smem (LDS.128 broadcast, 1 LDS : 4 FMA). 8-wide accumulator ILP.
// ---------------------------------------------------------------------------
__global__ __launch_bounds__(128) void mlp_kernel(
    const float* __restrict__ xyz, const float* __restrict__ feat,
    const float* __restrict__ w1, const float* __restrict__ b1,
    const float* __restrict__ w2, const float* __restrict__ b2,
    const float* __restrict__ w3, const float* __restrict__ b3,
    const float* __restrict__ newxyz, float* __restrict__ outf) {
    extern __shared__ float sm[];
    float* sw1 = sm;                 // 64 x 68 (padded)
    float* sw2 = sw1 + 64 * 68;      // 64 x 64
    float* sw3 = sw2 + 64 * 64;      // 128 x 64
    float* sb1 = sw3 + 128 * 64;     // 64
    float* sb2 = sb1 + 64;           // 64
    float* sb3 = sb2 + 64;           // 128

    const int tid = threadIdx.x;
    for (int i = tid; i < 64 * CIN; i += 128) sw1[(i / CIN) * 68 + (i % CIN)] = w1[i];
    for (int i = tid; i < 64 * 64; i += 128) sw2[i] = w2[i];
    for (int i = tid; i < 128 * 64; i += 128) sw3[i] = w3[i];
    if (tid < 64) {
        sb1[tid] = b1[tid];
        sb2[tid] = b2[tid];
    }
    if (tid < 128) sb3[tid] = b3[tid];
    __syncthreads();

    const int warp = tid >> 5, lane = tid & 31;
    const int pc = blockIdx.x * 4 + warp;  // global centroid id
    const int b = pc >> 10, p = pc & 1023;

    const int idx = g_nidx[pc * NS + lane];
    const float* P = xyz + ((size_t)b * NN + idx) * 3;
    const float* NXp = newxyz + (size_t)pc * 3;

    float in[CIN];
    in[0] = P[0] - NXp[0];
    in[1] = P[1] - NXp[1];
    in[2] = P[2] - NXp[2];
    const float4* F = (const float4*)(feat + ((size_t)b * NN + idx) * CF);
#pragma unroll
    for (int q = 0; q < 16; q++) {
        const float4 v = F[q];
        in[3 + 4 * q] = v.x;
        in[4 + 4 * q] = v.y;
        in[5 + 4 * q] = v.z;
        in[6 + 4 * q] = v.w;
    }

    float h1[64] __attribute__((aligned(16)));
#pragma unroll 1
    for (int o = 0; o < 64; o += 8) {
        float acc[8];
#pragma unroll
        for (int j = 0; j < 8; j++) acc[j] = sb1[o + j];
#pragma unroll
        for (int c = 0; c < 64; c += 4) {
#pragma unroll
            for (int j = 0; j < 8; j++) {
                const float4 w = *(const float4*)&sw1[(o + j) * 68 + c];
                acc[j] = fmaf(in[c + 0], w.x, acc[j]);
                acc[j] = fmaf(in[c + 1], w.y, acc[j]);
                acc[j] = fmaf(in[c + 2], w.z, acc[j]);
                acc[j] = fmaf(in[c + 3], w.w, acc[j]);
            }
        }
#pragma unroll
        for (int j = 0; j < 8; j++) {
            acc[j] = fmaf(in[64], sw1[(o + j) * 68 + 64], acc[j]);
            acc[j] = fmaf(in[65], sw1[(o + j) * 68 + 65], acc[j]);
            acc[j] = fmaf(in[66], sw1[(o + j) * 68 + 66], acc[j]);
            h1[o + j] = fmaxf(acc[j], 0.0f);
        }
    }

    float h2[64] __attribute__((aligned(16)));
#pragma unroll 1
    for (int o = 0; o < 64; o += 8) {
        float acc[8];
#pragma unroll
        for (int j = 0; j < 8; j++) acc[j] = sb2[o + j];
#pragma unroll
        for (int c = 0; c < 64; c += 4) {
            const float4 hv = *(const float4*)&h1[c];
#pragma unroll
            for (int j = 0; j < 8; j++) {
                const float4 w = *(const float4*)&sw2[(o + j) * 64 + c];
                acc[j] = fmaf(hv.x, w.x, acc[j]);
                acc[j] = fmaf(hv.y, w.y, acc[j]);
                acc[j] = fmaf(hv.z, w.z, acc[j]);
                acc[j] = fmaf(hv.w, w.w, acc[j]);
            }
        }
#pragma unroll
        for (int j = 0; j < 8; j++) h2[o + j] = fmaxf(acc[j], 0.0f);
    }

    const size_t obase = ((size_t)b * 128) * NPT + p;
#pragma unroll 1
    for (int o = 0; o < 128; o += 8) {
        float acc[8];
#pragma unroll
        for (int j = 0; j < 8; j++) acc[j] = sb3[o + j];
#pragma unroll
        for (int c = 0; c < 64; c += 4) {
            const float4 hv = *(const float4*)&h2[c];
#pragma unroll
            for (int j = 0; j < 8; j++) {
                const float4 w = *(const float4*)&sw3[(o + j) * 64 + c];
                acc[j] = fmaf(hv.x, w.x, acc[j]);
                acc[j] = fmaf(hv.y, w.y, acc[j]);
                acc[j] = fmaf(hv.z, w.z, acc[j]);
                acc[j] = fmaf(hv.w, w.w, acc[j]);
            }
        }
#pragma unroll
        for (int j = 0; j < 8; j++) {
            float v = fmaxf(acc[j], 0.0f);  // relu then max over samples
#pragma unroll
            for (int off = 16; off; off >>= 1)
                v = fmaxf(v, __shfl_xor_sync(0xffffffffu, v, off));
            if (lane == 0) outf[obase + (size_t)(o + j) * NPT] = v;
        }
    }
}

// ---------------------------------------------------------------------------
extern "C" void kernel_launch(void* const* d_in, const int* in_sizes, int n_in,
                              void* d_out, int out_size) {
    const float* xyz = (const float*)d_in[0];
    const float* feat = (const float*)d_in[1];
    const float* w1 = (const float*)d_in[2];
    const float* b1 = (const float*)d_in[3];
    const float* w2 = (const float*)d_in[4];
    const float* b2 = (const float*)d_in[5];
    const float* w3 = (const float*)d_in[6];
    const float* b3 = (const float*)d_in[7];

    float* out = (float*)d_out;
    float* newxyz = out;                  // (B, NPOINT, 3)
    float* outf = out + BB * NPT * 3;     // (B, 128, NPOINT)

    const int fps_smem = 8192 * 16 + 8192 * 8;  // 196608 B (full packed copy)
    const int mlp_smem = (64 * 68 + 64 * 64 + 128 * 64 + 64 + 64 + 128) * 4;  // 67584 B

    cudaFuncSetAttribute(fps_kernel, cudaFuncAttributeMaxDynamicSharedMemorySize, fps_smem);
    cudaFuncSetAttribute(mlp_kernel, cudaFuncAttributeMaxDynamicSharedMemorySize, mlp_smem);

    fps_kernel<<<BB * CL, 1024, fps_smem>>>(xyz, newxyz);
    ball_kernel<<<(BB * NPT * 32) / 256, 256>>>(xyz, newxyz);
    mlp_kernel<<<BB * NPT / 4, 128, mlp_smem>>>(xyz, feat, w1, b1, w2, b2, w3, b3, newxyz, outf);
}

// round 7
// speedup vs baseline: 1.1756x; 1.1756x over previous
#include <cuda_runtime.h>
#include <cstdint>
#include <cstddef>

#define BB 4
#define NN 16384
#define NPT 1024
#define NS 32
#define CF 64
#define CIN 67
#define CL 4  // CTAs per cluster (one cluster per batch)

// ---- packed f32x2 helpers (per-lane IEEE rn, identical to scalar __fadd_rn/__fmul_rn)
typedef unsigned long long u64;
__device__ __forceinline__ u64 f2_add(u64 a, u64 b) {
    u64 r;
    asm("add.rn.f32x2 %0, %1, %2;" : "=l"(r) : "l"(a), "l"(b));
    return r;
}
__device__ __forceinline__ u64 f2_mul(u64 a, u64 b) {
    u64 r;
    asm("mul.rn.f32x2 %0, %1, %2;" : "=l"(r) : "l"(a), "l"(b));
    return r;
}
__device__ __forceinline__ u64 f2_pack(float lo, float hi) {
    u64 r;
    asm("mov.b64 %0, {%1, %2};" : "=l"(r) : "f"(lo), "f"(hi));
    return r;
}
__device__ __forceinline__ float2 f2_unpack(u64 v) {
    float2 r;
    asm("mov.b64 {%0, %1}, %2;" : "=f"(r.x), "=f"(r.y) : "l"(v));
    return r;
}
__device__ __forceinline__ u64 umax64(u64 a, u64 b) { return a > b ? a : b; }
__device__ __forceinline__ uint32_t redux_max(uint32_t v) {
    uint32_t r;
    asm("redux.sync.max.u32 %0, %1, 0xffffffff;" : "=r"(r) : "r"(v));
    return r;
}
__device__ __forceinline__ uint32_t smem_u32(const void* p) {
    return (uint32_t)__cvta_generic_to_shared(p);
}
__device__ __forceinline__ void st_cluster_u64(uint32_t laddr, uint32_t rank, u64 v) {
    uint32_t r;
    asm volatile("mapa.shared::cluster.u32 %0, %1, %2;" : "=r"(r) : "r"(laddr), "r"(rank));
    asm volatile("st.relaxed.cluster.shared::cluster.u64 [%0], %1;" ::"r"(r), "l"(v)
                 : "memory");
}
__device__ __forceinline__ u64 ld_mbox(uint32_t laddr) {
    u64 v;
    asm volatile("ld.relaxed.cluster.shared::cta.u64 %0, [%1];" : "=l"(v) : "r"(laddr)
                 : "memory");
    return v;
}
__device__ __forceinline__ void st_vol_u64(u64* p, u64 v) {
    asm volatile("st.volatile.shared.u64 [%0], %1;" ::"r"(smem_u32(p)), "l"(v) : "memory");
}
__device__ __forceinline__ u64 ld_vol_u64(const u64* p) {
    u64 v;
    asm volatile("ld.volatile.shared.u64 %0, [%1];" : "=l"(v) : "r"(smem_u32(p)) : "memory");
    return v;
}
__device__ __forceinline__ void cluster_sync_all() {
    asm volatile("barrier.cluster.arrive.aligned;" ::: "memory");
    asm volatile("barrier.cluster.wait.aligned;" ::: "memory");
}

// message word: (p+1)(11b) << 53 | dist_bits(32b) << 21 | negidx(14b)
// Equal tags -> u64 max == (dist, -idx) lexicographic max == jnp.argmax semantics.

// ---------------------------------------------------------------------------
// FPS: 4-CTA cluster per batch (round-4 topology: ONE message per CTA/iter).
// Barrier-free intra-CTA handoff: warps 1..31 publish tagged partials to
// s_part and go straight to the remote poll; warp 0 spin-collects the 32
// partials, reduces, and publishes the CTA partial to all 4 ranks' mailboxes.
// Remote poll batch-loads all 4 words per attempt (no dependent spins).
// ---------------------------------------------------------------------------
__global__ __launch_bounds__(1024, 1) __cluster_dims__(CL, 1, 1)
void fps_kernel(const float* __restrict__ xyz, float* __restrict__ newxyz) {
    extern __shared__ unsigned char smraw[];
    ulonglong2* A = (ulonglong2*)smraw;            // 8192 x 16B = 128 KB
    u64* Z = (u64*)(smraw + 8192 * 16);            // 8192 x 8B  =  64 KB
    __shared__ u64 s_part[32];
    __shared__ u64 mbox[2][CL];                    // [parity][rank]

    const int b = blockIdx.x / CL;
    const int rank = blockIdx.x % CL;
    const int tid = threadIdx.x;
    const float* base = xyz + (size_t)b * NN * 3;

    // full packed copy (every CTA); slot s packs points (s, s+8192)
    for (int s = tid; s < 8192; s += 1024) {
        const int ia = s, ib = s + 8192;
        ulonglong2 av;
        av.x = f2_pack(base[3 * ia + 0], base[3 * ib + 0]);
        av.y = f2_pack(base[3 * ia + 1], base[3 * ib + 1]);
        A[s] = av;
        Z[s] = f2_pack(base[3 * ia + 2], base[3 * ib + 2]);
    }
    if (tid < 2 * CL) ((u64*)mbox)[tid] = 0;  // tags start at 1; 0 never matches
    if (tid < 32) s_part[tid] = 0;

    const int s0 = rank * 2048 + tid;  // this thread's two packed slots
    const int s1 = s0 + 1024;
    const uint32_t ni0a = (uint32_t)(16383 - s0);
    const uint32_t ni0b = (uint32_t)(16383 - (s0 + 8192));
    const uint32_t ni1a = (uint32_t)(16383 - s1);
    const uint32_t ni1b = (uint32_t)(16383 - (s1 + 8192));

    float2 d20 = make_float2(1e10f, 1e10f);
    float2 d21 = make_float2(1e10f, 1e10f);

    __syncthreads();
    cluster_sync_all();  // tiles + mailboxes initialized cluster-wide from here

    int f = 0;
    float* outp = newxyz + (size_t)b * NPT * 3;
    const int lane = tid & 31, wid = tid >> 5;
    const uint32_t mb0 = smem_u32(&mbox[0][0]);

    for (int p = 0; p < NPT; ++p) {
        // centroid fetch (local, full copy)
        const int fslot = f & 8191;
        const int fhalf = f >> 13;
        const ulonglong2 fa = A[fslot];
        const float2 fx = f2_unpack(fa.x);
        const float2 fy = f2_unpack(fa.y);
        const float2 fz = f2_unpack(Z[fslot]);
        const float cx = fhalf ? fx.y : fx.x;
        const float cy = fhalf ? fy.y : fy.x;
        const float cz = fhalf ? fz.y : fz.x;
        if (rank == 0 && tid == 0) {
            outp[3 * p + 0] = cx;
            outp[3 * p + 1] = cy;
            outp[3 * p + 2] = cz;
        }
        const u64 ncx = f2_pack(-cx, -cx);
        const u64 ncy = f2_pack(-cy, -cy);
        const u64 ncz = f2_pack(-cz, -cz);

        u64 loc;
        {
            const ulonglong2 av = A[s0];
            const u64 zv = Z[s0];
            const u64 dx = f2_add(av.x, ncx);
            const u64 dy = f2_add(av.y, ncy);
            const u64 dz = f2_add(zv, ncz);
            const float2 d =
                f2_unpack(f2_add(f2_add(f2_mul(dx, dx), f2_mul(dy, dy)), f2_mul(dz, dz)));
            d20.x = fminf(d20.x, d.x);
            d20.y = fminf(d20.y, d.y);
            const u64 k0 = ((u64)__float_as_uint(d20.x) << 21) | ni0a;
            const u64 k1 = ((u64)__float_as_uint(d20.y) << 21) | ni0b;
            loc = umax64(k0, k1);
        }
        {
            const ulonglong2 av = A[s1];
            const u64 zv = Z[s1];
            const u64 dx = f2_add(av.x, ncx);
            const u64 dy = f2_add(av.y, ncy);
            const u64 dz = f2_add(zv, ncz);
            const float2 d =
                f2_unpack(f2_add(f2_add(f2_mul(dx, dx), f2_mul(dy, dy)), f2_mul(dz, dz)));
            d21.x = fminf(d21.x, d.x);
            d21.y = fminf(d21.y, d.y);
            const u64 k0 = ((u64)__float_as_uint(d21.x) << 21) | ni1a;
            const u64 k1 = ((u64)__float_as_uint(d21.y) << 21) | ni1b;
            loc = umax64(loc, umax64(k0, k1));
        }

        // warp argmax via two redux ops
        const uint32_t dbits = (uint32_t)(loc >> 21);
        const uint32_t wmax = redux_max(dbits);
        const uint32_t cand = (dbits == wmax) ? (uint32_t)(loc & 0x3FFFu) : 0u;
        const uint32_t nmax = redux_max(cand);
        const u64 tag = (u64)(p + 1);
        const u64 msg = (tag << 53) | ((u64)wmax << 21) | nmax;

        const int par = p & 1;
        if (wid != 0) {
            if (lane == 0) st_vol_u64(&s_part[wid], msg);  // tagged local partial
        } else {
            // warp 0: spin-collect the 32 tagged partials (lane 0 uses its own)
            u64 part = msg;
            if (lane != 0) {
                do {
                    part = ld_vol_u64(&s_part[lane]);
                } while ((part >> 53) != tag);
            }
            const uint32_t d2b = (uint32_t)(part >> 21);
            const uint32_t m2 = redux_max(d2b);
            const uint32_t c2 = (d2b == m2) ? (uint32_t)(part & 0x3FFFu) : 0u;
            const uint32_t n2 = redux_max(c2);
            const u64 ctamsg = (tag << 53) | ((u64)m2 << 21) | n2;
            if (lane < CL)
                st_cluster_u64(mb0 + (uint32_t)(par * CL + rank) * 8u, (uint32_t)lane,
                               ctamsg);
        }

        // batch-poll the 4 mailbox words for this parity (independent loads)
        const uint32_t a0 = mb0 + (uint32_t)(par * CL) * 8u;
        u64 v0, v1, v2, v3;
        for (;;) {
            v0 = ld_mbox(a0);
            v1 = ld_mbox(a0 + 8u);
            v2 = ld_mbox(a0 + 16u);
            v3 = ld_mbox(a0 + 24u);
            if (((v0 >> 53) == tag) & ((v1 >> 53) == tag) & ((v2 >> 53) == tag) &
                ((v3 >> 53) == tag))
                break;
        }
        const u64 g = umax64(umax64(v0, v1), umax64(v2, v3));
        f = 16383 - (int)(g & 0x3FFFu);
    }
    cluster_sync_all();  // no CTA exits while peers may still store into it
}

// ---------------------------------------------------------------------------
// Fused ball query + gather + 3-layer MLP + max-pool.
// One warp per centroid (4 warps/block). Ball: index-ordered scan, first 32
// hits within radius (strict d2 < 0.01f), pad with first hit; indices handed
// to the MLP stage through per-warp smem. MLP: lane = sample, weights in smem
// (LDS.128 broadcast), 8-wide accumulator ILP, shfl max-pool.
// ---------------------------------------------------------------------------
__global__ __launch_bounds__(128) void ball_mlp_kernel(
    const float* __restrict__ xyz, const float* __restrict__ feat,
    const float* __restrict__ w1, const float* __restrict__ b1,
    const float* __restrict__ w2, const float* __restrict__ b2,
    const float* __restrict__ w3, const float* __restrict__ b3,
    const float* __restrict__ newxyz, float* __restrict__ outf) {
    extern __shared__ float sm[];
    float* sw1 = sm;                 // 64 x 68 (padded)
    float* sw2 = sw1 + 64 * 68;      // 64 x 64
    float* sw3 = sw2 + 64 * 64;      // 128 x 64
    float* sb1 = sw3 + 128 * 64;     // 64
    float* sb2 = sb1 + 64;           // 64
    float* sb3 = sb2 + 64;           // 128
    __shared__ int s_idx[4][NS];

    const int tid = threadIdx.x;
    for (int i = tid; i < 64 * CIN; i += 128) sw1[(i / CIN) * 68 + (i % CIN)] = w1[i];
    for (int i = tid; i < 64 * 64; i += 128) sw2[i] = w2[i];
    for (int i = tid; i < 128 * 64; i += 128) sw3[i] = w3[i];
    if (tid < 64) {
        sb1[tid] = b1[tid];
        sb2[tid] = b2[tid];
    }
    if (tid < 128) sb3[tid] = b3[tid];

    const int warp = tid >> 5, lane = tid & 31;
    const int pc = blockIdx.x * 4 + warp;  // global centroid id
    const int b = pc >> 10, p = pc & 1023;

    // ---- ball query ----
    const float* NXp = newxyz + (size_t)pc * 3;
    const float ccx = NXp[0], ccy = NXp[1], ccz = NXp[2];
    const float* px = xyz + (size_t)b * NN * 3;
    {
        int count = 0;
        int first = 0;
        bool havefirst = false;
        for (int bs = 0; bs < NN; bs += 32) {
            const int i = bs + lane;
            const float dx = __fadd_rn(px[3 * i + 0], -ccx);
            const float dy = __fadd_rn(px[3 * i + 1], -ccy);
            const float dz = __fadd_rn(px[3 * i + 2], -ccz);
            const float d2 =
                __fadd_rn(__fadd_rn(__fmul_rn(dx, dx), __fmul_rn(dy, dy)), __fmul_rn(dz, dz));
            const bool win = d2 < 0.01f;
            const unsigned m = __ballot_sync(0xffffffffu, win);
            if (m) {
                if (!havefirst) {
                    first = bs + __ffs(m) - 1;
                    havefirst = true;
                }
                const int slot = count + __popc(m & ((1u << lane) - 1u));
                if (win && slot < NS) s_idx[warp][slot] = i;
                count += __popc(m);
                if (count >= NS) break;
            }
        }
        if (lane >= count) s_idx[warp][lane] = first;
        __syncwarp();
    }
    __syncthreads();  // weights ready (also covers s_idx)

    const int idx = s_idx[warp][lane];
    const float* P = xyz + ((size_t)b * NN + idx) * 3;

    float in[CIN];
    in[0] = P[0] - ccx;
    in[1] = P[1] - ccy;
    in[2] = P[2] - ccz;
    const float4* F = (const float4*)(feat + ((size_t)b * NN + idx) * CF);
#pragma unroll
    for (int q = 0; q < 16; q++) {
        const float4 v = F[q];
        in[3 + 4 * q] = v.x;
        in[4 + 4 * q] = v.y;
        in[5 + 4 * q] = v.z;
        in[6 + 4 * q] = v.w;
    }

    float h1[64] __attribute__((aligned(16)));
#pragma unroll 1
    for (int o = 0; o < 64; o += 8) {
        float acc[8];
#pragma unroll
        for (int j = 0; j < 8; j++) acc[j] = sb1[o + j];
#pragma unroll
        for (int c = 0; c < 64; c += 4) {
#pragma unroll
            for (int j = 0; j < 8; j++) {
                const float4 w = *(const float4*)&sw1[(o + j) * 68 + c];
                acc[j] = fmaf(in[c + 0], w.x, acc[j]);
                acc[j] = fmaf(in[c + 1], w.y, acc[j]);
                acc[j] = fmaf(in[c + 2], w.z, acc[j]);
                acc[j] = fmaf(in[c + 3], w.w, acc[j]);
            }
        }
#pragma unroll
        for (int j = 0; j < 8; j++) {
            acc[j] = fmaf(in[64], sw1[(o + j) * 68 + 64], acc[j]);
            acc[j] = fmaf(in[65], sw1[(o + j) * 68 + 65], acc[j]);
            acc[j] = fmaf(in[66], sw1[(o + j) * 68 + 66], acc[j]);
            h1[o + j] = fmaxf(acc[j], 0.0f);
        }
    }

    float h2[64] __attribute__((aligned(16)));
#pragma unroll 1
    for (int o = 0; o < 64; o += 8) {
        float acc[8];
#pragma unroll
        for (int j = 0; j < 8; j++) acc[j] = sb2[o + j];
#pragma unroll
        for (int c = 0; c < 64; c += 4) {
            const float4 hv = *(const float4*)&h1[c];
#pragma unroll
            for (int j = 0; j < 8; j++) {
                const float4 w = *(const float4*)&sw2[(o + j) * 64 + c];
                acc[j] = fmaf(hv.x, w.x, acc[j]);
                acc[j] = fmaf(hv.y, w.y, acc[j]);
                acc[j] = fmaf(hv.z, w.z, acc[j]);
                acc[j] = fmaf(hv.w, w.w, acc[j]);
            }
        }
#pragma unroll
        for (int j = 0; j < 8; j++) h2[o + j] = fmaxf(acc[j], 0.0f);
    }

    const size_t obase = ((size_t)b * 128) * NPT + p;
#pragma unroll 1
    for (int o = 0; o < 128; o += 8) {
        float acc[8];
#pragma unroll
        for (int j = 0; j < 8; j++) acc[j] = sb3[o + j];
#pragma unroll
        for (int c = 0; c < 64; c += 4) {
            const float4 hv = *(const float4*)&h2[c];
#pragma unroll
            for (int j = 0; j < 8; j++) {
                const float4 w = *(const float4*)&sw3[(o + j) * 64 + c];
                acc[j] = fmaf(hv.x, w.x, acc[j]);
                acc[j] = fmaf(hv.y, w.y, acc[j]);
                acc[j] = fmaf(hv.z, w.z, acc[j]);
                acc[j] = fmaf(hv.w, w.w, acc[j]);
            }
        }
#pragma unroll
        for (int j = 0; j < 8; j++) {
            float v = fmaxf(acc[j], 0.0f);  // relu then max over samples
#pragma unroll
            for (int off = 16; off; off >>= 1)
                v = fmaxf(v, __shfl_xor_sync(0xffffffffu, v, off));
            if (lane == 0) outf[obase + (size_t)(o + j) * NPT] = v;
        }
    }
}

// ---------------------------------------------------------------------------
extern "C" void kernel_launch(void* const* d_in, const int* in_sizes, int n_in,
                              void* d_out, int out_size) {
    const float* xyz = (const float*)d_in[0];
    const float* feat = (const float*)d_in[1];
    const float* w1 = (const float*)d_in[2];
    const float* b1 = (const float*)d_in[3];
    const float* w2 = (const float*)d_in[4];
    const float* b2 = (const float*)d_in[5];
    const float* w3 = (const float*)d_in[6];
    const float* b3 = (const float*)d_in[7];

    float* out = (float*)d_out;
    float* newxyz = out;                  // (B, NPOINT, 3)
    float* outf = out + BB * NPT * 3;     // (B, 128, NPOINT)

    const int fps_smem = 8192 * 16 + 8192 * 8;  // 196608 B (full packed copy)
    const int mlp_smem = (64 * 68 + 64 * 64 + 128 * 64 + 64 + 64 + 128) * 4;  // 67584 B

    cudaFuncSetAttribute(fps_kernel, cudaFuncAttributeMaxDynamicSharedMemorySize, fps_smem);
    cudaFuncSetAttribute(ball_mlp_kernel, cudaFuncAttributeMaxDynamicSharedMemorySize,
                         mlp_smem);

    fps_kernel<<<BB * CL, 1024, fps_smem>>>(xyz, newxyz);
    ball_mlp_kernel<<<BB * NPT / 4, 128, mlp_smem>>>(xyz, feat, w1, b1, w2, b2, w3, b3,
                                                     newxyz, outf);
}

// round 8
// speedup vs baseline: 2.0417x; 1.7367x over previous
#include <cuda_runtime.h>
#include <cstdint>
#include <cstddef>

#define BB 4
#define NN 16384
#define NPT 1024
#define NS 32
#define CF 64
#define CIN 67
#define CL 4  // CTAs per cluster (one cluster per batch)

// scratch: neighbor indices (B, NPOINT, NSAMPLE)
__device__ int g_nidx[BB * NPT * NS];

// ---- packed f32x2 helpers (per-lane IEEE rn, identical to scalar __fadd_rn/__fmul_rn)
typedef unsigned long long u64;
__device__ __forceinline__ u64 f2_add(u64 a, u64 b) {
    u64 r;
    asm("add.rn.f32x2 %0, %1, %2;" : "=l"(r) : "l"(a), "l"(b));
    return r;
}
__device__ __forceinline__ u64 f2_mul(u64 a, u64 b) {
    u64 r;
    asm("mul.rn.f32x2 %0, %1, %2;" : "=l"(r) : "l"(a), "l"(b));
    return r;
}
__device__ __forceinline__ u64 f2_pack(float lo, float hi) {
    u64 r;
    asm("mov.b64 %0, {%1, %2};" : "=l"(r) : "f"(lo), "f"(hi));
    return r;
}
__device__ __forceinline__ float2 f2_unpack(u64 v) {
    float2 r;
    asm("mov.b64 {%0, %1}, %2;" : "=f"(r.x), "=f"(r.y) : "l"(v));
    return r;
}
__device__ __forceinline__ u64 umax64(u64 a, u64 b) { return a > b ? a : b; }
__device__ __forceinline__ uint32_t redux_max(uint32_t v) {
    uint32_t r;
    asm("redux.sync.max.u32 %0, %1, 0xffffffff;" : "=r"(r) : "r"(v));
    return r;
}
__device__ __forceinline__ uint32_t smem_u32(const void* p) {
    return (uint32_t)__cvta_generic_to_shared(p);
}
__device__ __forceinline__ void st_cluster_u64(uint32_t laddr, uint32_t rank, u64 v) {
    uint32_t r;
    asm volatile("mapa.shared::cluster.u32 %0, %1, %2;" : "=r"(r) : "r"(laddr), "r"(rank));
    asm volatile("st.relaxed.cluster.shared::cluster.u64 [%0], %1;" ::"r"(r), "l"(v)
                 : "memory");
}
__device__ __forceinline__ u64 ld_mbox(uint32_t laddr) {
    u64 v;
    asm volatile("ld.relaxed.cluster.shared::cta.u64 %0, [%1];" : "=l"(v) : "r"(laddr)
                 : "memory");
    return v;
}
__device__ __forceinline__ void cluster_sync_all() {
    asm volatile("barrier.cluster.arrive.aligned;" ::: "memory");
    asm volatile("barrier.cluster.wait.aligned;" ::: "memory");
}

// mailbox word: (p+1)(11b) << 53 | dist_bits(32b) << 21 | negidx(14b)
// Equal tags -> u64 max == (dist, -idx) lexicographic max == jnp.argmax semantics.

// ---------------------------------------------------------------------------
// FPS: 4-CTA cluster per batch (round-4 topology: ONE message per CTA/iter,
// __syncthreads + warp-0 stage-2 + tagged DSMEM mailboxes). Only change vs
// round 4: the mailbox poll batch-loads all 4 words per attempt instead of
// running 4 dependent spin loops.
// ---------------------------------------------------------------------------
__global__ __launch_bounds__(1024, 1) __cluster_dims__(CL, 1, 1)
void fps_kernel(const float* __restrict__ xyz, float* __restrict__ newxyz) {
    extern __shared__ unsigned char smraw[];
    ulonglong2* A = (ulonglong2*)smraw;            // 8192 x 16B = 128 KB
    u64* Z = (u64*)(smraw + 8192 * 16);            // 8192 x 8B  =  64 KB
    __shared__ u64 s_part[32];
    __shared__ u64 mbox[2][CL];                    // [parity][rank]

    const int b = blockIdx.x / CL;
    const int rank = blockIdx.x % CL;
    const int tid = threadIdx.x;
    const float* base = xyz + (size_t)b * NN * 3;

    // full packed copy (every CTA); slot s packs points (s, s+8192)
    for (int s = tid; s < 8192; s += 1024) {
        const int ia = s, ib = s + 8192;
        ulonglong2 av;
        av.x = f2_pack(base[3 * ia + 0], base[3 * ib + 0]);
        av.y = f2_pack(base[3 * ia + 1], base[3 * ib + 1]);
        A[s] = av;
        Z[s] = f2_pack(base[3 * ia + 2], base[3 * ib + 2]);
    }
    if (tid < 2 * CL) ((u64*)mbox)[tid] = 0;  // tags start at 1; 0 never matches

    const int s0 = rank * 2048 + tid;  // this thread's two packed slots
    const int s1 = s0 + 1024;
    const uint32_t ni0a = (uint32_t)(16383 - s0);
    const uint32_t ni0b = (uint32_t)(16383 - (s0 + 8192));
    const uint32_t ni1a = (uint32_t)(16383 - s1);
    const uint32_t ni1b = (uint32_t)(16383 - (s1 + 8192));

    float2 d20 = make_float2(1e10f, 1e10f);
    float2 d21 = make_float2(1e10f, 1e10f);

    __syncthreads();
    cluster_sync_all();  // tiles + mailboxes initialized cluster-wide from here

    int f = 0;
    float* outp = newxyz + (size_t)b * NPT * 3;
    const int lane = tid & 31, wid = tid >> 5;
    const uint32_t mb0 = smem_u32(&mbox[0][0]);

    for (int p = 0; p < NPT; ++p) {
        // centroid fetch (local, full copy)
        const int fslot = f & 8191;
        const int fhalf = f >> 13;
        const ulonglong2 fa = A[fslot];
        const float2 fx = f2_unpack(fa.x);
        const float2 fy = f2_unpack(fa.y);
        const float2 fz = f2_unpack(Z[fslot]);
        const float cx = fhalf ? fx.y : fx.x;
        const float cy = fhalf ? fy.y : fy.x;
        const float cz = fhalf ? fz.y : fz.x;
        if (rank == 0 && tid == 0) {
            outp[3 * p + 0] = cx;
            outp[3 * p + 1] = cy;
            outp[3 * p + 2] = cz;
        }
        const u64 ncx = f2_pack(-cx, -cx);
        const u64 ncy = f2_pack(-cy, -cy);
        const u64 ncz = f2_pack(-cz, -cz);

        u64 loc;
        {
            const ulonglong2 av = A[s0];
            const u64 zv = Z[s0];
            const u64 dx = f2_add(av.x, ncx);
            const u64 dy = f2_add(av.y, ncy);
            const u64 dz = f2_add(zv, ncz);
            const float2 d =
                f2_unpack(f2_add(f2_add(f2_mul(dx, dx), f2_mul(dy, dy)), f2_mul(dz, dz)));
            d20.x = fminf(d20.x, d.x);
            d20.y = fminf(d20.y, d.y);
            const u64 k0 = ((u64)__float_as_uint(d20.x) << 21) | ni0a;
            const u64 k1 = ((u64)__float_as_uint(d20.y) << 21) | ni0b;
            loc = umax64(k0, k1);
        }
        {
            const ulonglong2 av = A[s1];
            const u64 zv = Z[s1];
            const u64 dx = f2_add(av.x, ncx);
            const u64 dy = f2_add(av.y, ncy);
            const u64 dz = f2_add(zv, ncz);
            const float2 d =
                f2_unpack(f2_add(f2_add(f2_mul(dx, dx), f2_mul(dy, dy)), f2_mul(dz, dz)));
            d21.x = fminf(d21.x, d.x);
            d21.y = fminf(d21.y, d.y);
            const u64 k0 = ((u64)__float_as_uint(d21.x) << 21) | ni1a;
            const u64 k1 = ((u64)__float_as_uint(d21.y) << 21) | ni1b;
            loc = umax64(loc, umax64(k0, k1));
        }

        // warp argmax via two redux ops
        {
            const uint32_t dbits = (uint32_t)(loc >> 21);
            const uint32_t wmax = redux_max(dbits);
            const uint32_t cand = (dbits == wmax) ? (uint32_t)(loc & 0x3FFFu) : 0u;
            const uint32_t nmax = redux_max(cand);
            if (lane == 0) s_part[wid] = ((u64)wmax << 21) | nmax;
        }
        __syncthreads();

        const int par = p & 1;
        const u64 tag = (u64)(p + 1);
        if (wid == 0) {
            // stage 2: reduce 32 CTA partials, publish to all 4 ranks (tagged)
            const u64 v = s_part[lane];
            const uint32_t dbits = (uint32_t)(v >> 21);
            const uint32_t wmax = redux_max(dbits);
            const uint32_t cand = (dbits == wmax) ? (uint32_t)(v & 0x3FFFu) : 0u;
            const uint32_t nmax = redux_max(cand);
            const u64 msg = (tag << 53) | ((u64)wmax << 21) | nmax;
            if (lane < CL)
                st_cluster_u64(mb0 + (uint32_t)(par * CL + rank) * 8u, (uint32_t)lane, msg);
        }

        // batch-poll the 4 mailbox words for this parity (independent loads)
        const uint32_t a0 = mb0 + (uint32_t)(par * CL) * 8u;
        u64 v0, v1, v2, v3;
        for (;;) {
            v0 = ld_mbox(a0);
            v1 = ld_mbox(a0 + 8u);
            v2 = ld_mbox(a0 + 16u);
            v3 = ld_mbox(a0 + 24u);
            if (((v0 >> 53) == tag) & ((v1 >> 53) == tag) & ((v2 >> 53) == tag) &
                ((v3 >> 53) == tag))
                break;
        }
        const u64 g = umax64(umax64(v0, v1), umax64(v2, v3));
        f = 16383 - (int)(g & 0x3FFFu);
    }
    cluster_sync_all();  // no CTA exits while peers may still store into it
}

// ---------------------------------------------------------------------------
// Ball query: one warp per centroid, 256-thr blocks, no smem (high occupancy).
// Scan points in index order, append the first 32 within radius
// (strict d2 < 0.01f), pad with the first hit.
// ---------------------------------------------------------------------------
__global__ __launch_bounds__(256) void ball_kernel(const float* __restrict__ xyz,
                                                   const float* __restrict__ newxyz) {
    const int gw = (int)((blockIdx.x * blockDim.x + threadIdx.x) >> 5);
    const int lane = threadIdx.x & 31;
    if (gw >= BB * NPT) return;
    const int b = gw >> 10;

    const float* nx = newxyz + (size_t)gw * 3;
    const float cx = nx[0], cy = nx[1], cz = nx[2];
    const float* px = xyz + (size_t)b * NN * 3;
    int* out = g_nidx + (size_t)gw * NS;

    int count = 0;
    int first = 0;
    bool havefirst = false;

    for (int bs = 0; bs < NN; bs += 32) {
        const int i = bs + lane;
        const float dx = __fadd_rn(px[3 * i + 0], -cx);
        const float dy = __fadd_rn(px[3 * i + 1], -cy);
        const float dz = __fadd_rn(px[3 * i + 2], -cz);
        const float d2 =
            __fadd_rn(__fadd_rn(__fmul_rn(dx, dx), __fmul_rn(dy, dy)), __fmul_rn(dz, dz));
        const bool win = d2 < 0.01f;
        const unsigned m = __ballot_sync(0xffffffffu, win);
        if (m) {
            if (!havefirst) {
                first = bs + __ffs(m) - 1;
                havefirst = true;
            }
            const int slot = count + __popc(m & ((1u << lane) - 1u));
            if (win && slot < NS) out[slot] = i;
            count += __popc(m);
            if (count >= NS) break;
        }
    }
    if (lane >= count) out[lane] = first;  // pad (count<32 case); no-op if count>=32
}

// ---------------------------------------------------------------------------
// Gather + 3-layer MLP + max-pool. One warp per centroid, lane = sample.
// Spill-free: h1 staged in smem (per-thread column, stride 68 floats,
// STS/LDS.128, no cross-thread sharing so no barrier needed); h2 in regs.
// Weights in smem (LDS.128 broadcast). 8-wide accumulator ILP.
// ---------------------------------------------------------------------------
__global__ __launch_bounds__(128) void mlp_kernel(
    const float* __restrict__ xyz, const float* __restrict__ feat,
    const float* __restrict__ w1, const float* __restrict__ b1,
    const float* __restrict__ w2, const float* __restrict__ b2,
    const float* __restrict__ w3, const float* __restrict__ b3,
    const float* __restrict__ newxyz, float* __restrict__ outf) {
    extern __shared__ float sm[];
    float* sw1 = sm;                 // 64 x 68 (padded)
    float* sw2 = sw1 + 64 * 68;      // 64 x 64
    float* sw3 = sw2 + 64 * 64;      // 128 x 64
    float* sb1 = sw3 + 128 * 64;     // 64
    float* sb2 = sb1 + 64;           // 64
    float* sb3 = sb2 + 64;           // 128
    float* sh1 = sb3 + 128;          // 128 threads x 68 floats (h1 staging)

    const int tid = threadIdx.x;
    for (int i = tid; i < 64 * CIN; i += 128) sw1[(i / CIN) * 68 + (i % CIN)] = w1[i];
    for (int i = tid; i < 64 * 64; i += 128) sw2[i] = w2[i];
    for (int i = tid; i < 128 * 64; i += 128) sw3[i] = w3[i];
    if (tid < 64) {
        sb1[tid] = b1[tid];
        sb2[tid] = b2[tid];
    }
    if (tid < 128) sb3[tid] = b3[tid];
    __syncthreads();

    const int warp = tid >> 5, lane = tid & 31;
    const int pc = blockIdx.x * 4 + warp;  // global centroid id
    const int b = pc >> 10, p = pc & 1023;

    const int idx = g_nidx[pc * NS + lane];
    const float* P = xyz + ((size_t)b * NN + idx) * 3;
    const float* NXp = newxyz + (size_t)pc * 3;

    float in[CIN];
    in[0] = P[0] - NXp[0];
    in[1] = P[1] - NXp[1];
    in[2] = P[2] - NXp[2];
    const float4* F = (const float4*)(feat + ((size_t)b * NN + idx) * CF);
#pragma unroll
    for (int q = 0; q < 16; q++) {
        const float4 v = F[q];
        in[3 + 4 * q] = v.x;
        in[4 + 4 * q] = v.y;
        in[5 + 4 * q] = v.z;
        in[6 + 4 * q] = v.w;
    }

    float* myh1 = sh1 + tid * 68;  // 272B stride, 16B aligned

    // ---- layer 1: in[67] (regs) -> h1 (smem staging) ----
#pragma unroll 1
    for (int o = 0; o < 64; o += 8) {
        float acc[8];
#pragma unroll
        for (int j = 0; j < 8; j++) acc[j] = sb1[o + j];
#pragma unroll
        for (int c = 0; c < 64; c += 4) {
#pragma unroll
            for (int j = 0; j < 8; j++) {
                const float4 w = *(const float4*)&sw1[(o + j) * 68 + c];
                acc[j] = fmaf(in[c + 0], w.x, acc[j]);
                acc[j] = fmaf(in[c + 1], w.y, acc[j]);
                acc[j] = fmaf(in[c + 2], w.z, acc[j]);
                acc[j] = fmaf(in[c + 3], w.w, acc[j]);
            }
        }
#pragma unroll
        for (int j = 0; j < 8; j++) {
            acc[j] = fmaf(in[64], sw1[(o + j) * 68 + 64], acc[j]);
            acc[j] = fmaf(in[65], sw1[(o + j) * 68 + 65], acc[j]);
            acc[j] = fmaf(in[66], sw1[(o + j) * 68 + 66], acc[j]);
            acc[j] = fmaxf(acc[j], 0.0f);
        }
        *(float4*)&myh1[o + 0] = make_float4(acc[0], acc[1], acc[2], acc[3]);
        *(float4*)&myh1[o + 4] = make_float4(acc[4], acc[5], acc[6], acc[7]);
    }

    // ---- layer 2: h1 (smem) -> h2 (regs) ----
    float h2[64] __attribute__((aligned(16)));
#pragma unroll 1
    for (int o = 0; o < 64; o += 8) {
        float acc[8];
#pragma unroll
        for (int j = 0; j < 8; j++) acc[j] = sb2[o + j];
#pragma unroll
        for (int c = 0; c < 64; c += 4) {
            const float4 hv = *(const float4*)&myh1[c];
#pragma unroll
            for (int j = 0; j < 8; j++) {
                const float4 w = *(const float4*)&sw2[(o + j) * 64 + c];
                acc[j] = fmaf(hv.x, w.x, acc[j]);
                acc[j] = fmaf(hv.y, w.y, acc[j]);
                acc[j] = fmaf(hv.z, w.z, acc[j]);
                acc[j] = fmaf(hv.w, w.w, acc[j]);
            }
        }
#pragma unroll
        for (int j = 0; j < 8; j++) h2[o + j] = fmaxf(acc[j], 0.0f);
    }

    // ---- layer 3: h2 (regs) -> out, fused relu + sample max-pool ----
    const size_t obase = ((size_t)b * 128) * NPT + p;
#pragma unroll 1
    for (int o = 0; o < 128; o += 8) {
        float acc[8];
#pragma unroll
        for (int j = 0; j < 8; j++) acc[j] = sb3[o + j];
#pragma unroll
        for (int c = 0; c < 64; c += 4) {
            const float4 hv = *(const float4*)&h2[c];
#pragma unroll
            for (int j = 0; j < 8; j++) {
                const float4 w = *(const float4*)&sw3[(o + j) * 64 + c];
                acc[j] = fmaf(hv.x, w.x, acc[j]);
                acc[j] = fmaf(hv.y, w.y, acc[j]);
                acc[j] = fmaf(hv.z, w.z, acc[j]);
                acc[j] = fmaf(hv.w, w.w, acc[j]);
            }
        }
#pragma unroll
        for (int j = 0; j < 8; j++) {
            float v = fmaxf(acc[j], 0.0f);  // relu then max over samples
#pragma unroll
            for (int off = 16; off; off >>= 1)
                v = fmaxf(v, __shfl_xor_sync(0xffffffffu, v, off));
            if (lane == 0) outf[obase + (size_t)(o + j) * NPT] = v;
        }
    }
}

// ---------------------------------------------------------------------------
extern "C" void kernel_launch(void* const* d_in, const int* in_sizes, int n_in,
                              void* d_out, int out_size) {
    const float* xyz = (const float*)d_in[0];
    const float* feat = (const float*)d_in[1];
    const float* w1 = (const float*)d_in[2];
    const float* b1 = (const float*)d_in[3];
    const float* w2 = (const float*)d_in[4];
    const float* b2 = (const float*)d_in[5];
    const float* w3 = (const float*)d_in[6];
    const float* b3 = (const float*)d_in[7];

    float* out = (float*)d_out;
    float* newxyz = out;                  // (B, NPOINT, 3)
    float* outf = out + BB * NPT * 3;     // (B, 128, NPOINT)

    const int fps_smem = 8192 * 16 + 8192 * 8;  // 196608 B (full packed copy)
    const int mlp_smem =
        (64 * 68 + 64 * 64 + 128 * 64 + 64 + 64 + 128 + 128 * 68) * 4;  // 102400 B

    cudaFuncSetAttribute(fps_kernel, cudaFuncAttributeMaxDynamicSharedMemorySize, fps_smem);
    cudaFuncSetAttribute(mlp_kernel, cudaFuncAttributeMaxDynamicSharedMemorySize, mlp_smem);

    fps_kernel<<<BB * CL, 1024, fps_smem>>>(xyz, newxyz);
    ball_kernel<<<(BB * NPT * 32) / 256, 256>>>(xyz, newxyz);
    mlp_kernel<<<BB * NPT / 4, 128, mlp_smem>>>(xyz, feat, w1, b1, w2, b2, w3, b3, newxyz, outf);
}

// round 9
// speedup vs baseline: 2.0730x; 1.0154x over previous
#include <cuda_runtime.h>
#include <cstdint>
#include <cstddef>

#define BB 4
#define NN 16384
#define NPT 1024
#define NS 32
#define CF 64
#define CIN 67
#define CL 4  // CTAs per cluster (one cluster per batch)

// scratch: neighbor indices (B, NPOINT, NSAMPLE)
__device__ int g_nidx[BB * NPT * NS];

// ---- packed f32x2 helpers (per-lane IEEE rn, identical to scalar __fadd_rn/__fmul_rn)
typedef unsigned long long u64;
__device__ __forceinline__ u64 f2_add(u64 a, u64 b) {
    u64 r;
    asm("add.rn.f32x2 %0, %1, %2;" : "=l"(r) : "l"(a), "l"(b));
    return r;
}
__device__ __forceinline__ u64 f2_mul(u64 a, u64 b) {
    u64 r;
    asm("mul.rn.f32x2 %0, %1, %2;" : "=l"(r) : "l"(a), "l"(b));
    return r;
}
__device__ __forceinline__ u64 f2_pack(float lo, float hi) {
    u64 r;
    asm("mov.b64 %0, {%1, %2};" : "=l"(r) : "f"(lo), "f"(hi));
    return r;
}
__device__ __forceinline__ float2 f2_unpack(u64 v) {
    float2 r;
    asm("mov.b64 {%0, %1}, %2;" : "=f"(r.x), "=f"(r.y) : "l"(v));
    return r;
}
__device__ __forceinline__ u64 umax64(u64 a, u64 b) { return a > b ? a : b; }
__device__ __forceinline__ uint32_t redux_max(uint32_t v) {
    uint32_t r;
    asm("redux.sync.max.u32 %0, %1, 0xffffffff;" : "=r"(r) : "r"(v));
    return r;
}
__device__ __forceinline__ uint32_t smem_u32(const void* p) {
    return (uint32_t)__cvta_generic_to_shared(p);
}
__device__ __forceinline__ void st_cluster_u64(uint32_t laddr, uint32_t rank, u64 v) {
    uint32_t r;
    asm volatile("mapa.shared::cluster.u32 %0, %1, %2;" : "=r"(r) : "r"(laddr), "r"(rank));
    asm volatile("st.relaxed.cluster.shared::cluster.u64 [%0], %1;" ::"r"(r), "l"(v)
                 : "memory");
}
__device__ __forceinline__ void mbar_arrive_remote(uint32_t laddr, uint32_t rank) {
    asm volatile(
        "{\n\t"
        ".reg .b32 r;\n\t"
        "mapa.shared::cluster.u32 r, %0, %1;\n\t"
        "mbarrier.arrive.release.cluster.shared::cluster.b64 _, [r];\n\t"
        "}" ::"r"(laddr),
        "r"(rank)
        : "memory");
}
__device__ __forceinline__ void mbar_wait_parity(uint32_t laddr, uint32_t parity) {
    uint32_t done;
    do {
        asm volatile(
            "{\n\t"
            ".reg .pred p;\n\t"
            "mbarrier.try_wait.parity.acquire.cluster.shared::cta.b64 p, [%1], %2, 0x989680;\n\t"
            "selp.b32 %0, 1, 0, p;\n\t"
            "}"
            : "=r"(done)
            : "r"(laddr), "r"(parity)
            : "memory");
    } while (!done);
}
__device__ __forceinline__ void cluster_sync_all() {
    asm volatile("barrier.cluster.arrive.aligned;" ::: "memory");
    asm volatile("barrier.cluster.wait.aligned;" ::: "memory");
}

// mailbox word: dist_bits(32b) << 21 | negidx(14b)
// u64 max == (dist, -idx) lexicographic max == jnp.argmax first-max semantics.

// ---------------------------------------------------------------------------
// FPS: 4-CTA cluster per batch. Full packed xyz copy per CTA (slot s packs
// points (s, s+8192)); each CTA updates dists for its own 4096 points, whose
// coords are HOISTED into registers (loop-invariant). Intra-CTA: redux warp
// argmax -> s_part -> __syncthreads -> warp-0 stage-2. Cross-CTA: warp 0
// stores the CTA partial into every rank's parity-buffered mailbox and does a
// release-arrive on that rank's mbarrier (arrive count = 4); all threads
// sleep-wait on the local mbarrier parity (no load spinning), then read the
// 4 words with plain LDS.
// ---------------------------------------------------------------------------
__global__ __launch_bounds__(1024, 1) __cluster_dims__(CL, 1, 1)
void fps_kernel(const float* __restrict__ xyz, float* __restrict__ newxyz) {
    extern __shared__ unsigned char smraw[];
    ulonglong2* A = (ulonglong2*)smraw;            // 8192 x 16B = 128 KB
    u64* Z = (u64*)(smraw + 8192 * 16);            // 8192 x 8B  =  64 KB
    __shared__ u64 s_part[32];
    __shared__ u64 mbox[2][CL];                    // [parity][rank]
    __shared__ __align__(8) u64 s_mbar;            // arrive count = CL

    const int b = blockIdx.x / CL;
    const int rank = blockIdx.x % CL;
    const int tid = threadIdx.x;
    const float* base = xyz + (size_t)b * NN * 3;

    // full packed copy (every CTA)
    for (int s = tid; s < 8192; s += 1024) {
        const int ia = s, ib = s + 8192;
        ulonglong2 av;
        av.x = f2_pack(base[3 * ia + 0], base[3 * ib + 0]);
        av.y = f2_pack(base[3 * ia + 1], base[3 * ib + 1]);
        A[s] = av;
        Z[s] = f2_pack(base[3 * ia + 2], base[3 * ib + 2]);
    }
    if (tid == 0) {
        asm volatile("mbarrier.init.shared.b64 [%0], %1;" ::"r"(smem_u32(&s_mbar)),
                     "r"((uint32_t)CL)
                     : "memory");
    }

    const int s0 = rank * 2048 + tid;  // this thread's two packed slots
    const int s1 = s0 + 1024;
    const uint32_t ni0a = (uint32_t)(16383 - s0);
    const uint32_t ni0b = (uint32_t)(16383 - (s0 + 8192));
    const uint32_t ni1a = (uint32_t)(16383 - s1);
    const uint32_t ni1b = (uint32_t)(16383 - (s1 + 8192));

    float2 d20 = make_float2(1e10f, 1e10f);
    float2 d21 = make_float2(1e10f, 1e10f);

    __syncthreads();
    cluster_sync_all();  // tiles + mbarriers initialized cluster-wide from here

    // hoist loop-invariant point coords into registers
    const ulonglong2 av0 = A[s0];
    const u64 zv0 = Z[s0];
    const ulonglong2 av1 = A[s1];
    const u64 zv1 = Z[s1];

    int f = 0;
    float* outp = newxyz + (size_t)b * NPT * 3;
    const int lane = tid & 31, wid = tid >> 5;
    const uint32_t mb0 = smem_u32(&mbox[0][0]);
    const uint32_t mbar_a = smem_u32(&s_mbar);

    for (int p = 0; p < NPT; ++p) {
        // centroid fetch (local, full copy)
        const int fslot = f & 8191;
        const int fhalf = f >> 13;
        const ulonglong2 fa = A[fslot];
        const float2 fx = f2_unpack(fa.x);
        const float2 fy = f2_unpack(fa.y);
        const float2 fz = f2_unpack(Z[fslot]);
        const float cx = fhalf ? fx.y : fx.x;
        const float cy = fhalf ? fy.y : fy.x;
        const float cz = fhalf ? fz.y : fz.x;
        if (rank == 0 && tid == 0) {
            outp[3 * p + 0] = cx;
            outp[3 * p + 1] = cy;
            outp[3 * p + 2] = cz;
        }
        const u64 ncx = f2_pack(-cx, -cx);
        const u64 ncy = f2_pack(-cy, -cy);
        const u64 ncz = f2_pack(-cz, -cz);

        u64 loc;
        {
            const u64 dx = f2_add(av0.x, ncx);
            const u64 dy = f2_add(av0.y, ncy);
            const u64 dz = f2_add(zv0, ncz);
            const float2 d =
                f2_unpack(f2_add(f2_add(f2_mul(dx, dx), f2_mul(dy, dy)), f2_mul(dz, dz)));
            d20.x = fminf(d20.x, d.x);
            d20.y = fminf(d20.y, d.y);
            const u64 k0 = ((u64)__float_as_uint(d20.x) << 21) | ni0a;
            const u64 k1 = ((u64)__float_as_uint(d20.y) << 21) | ni0b;
            loc = umax64(k0, k1);
        }
        {
            const u64 dx = f2_add(av1.x, ncx);
            const u64 dy = f2_add(av1.y, ncy);
            const u64 dz = f2_add(zv1, ncz);
            const float2 d =
                f2_unpack(f2_add(f2_add(f2_mul(dx, dx), f2_mul(dy, dy)), f2_mul(dz, dz)));
            d21.x = fminf(d21.x, d.x);
            d21.y = fminf(d21.y, d.y);
            const u64 k0 = ((u64)__float_as_uint(d21.x) << 21) | ni1a;
            const u64 k1 = ((u64)__float_as_uint(d21.y) << 21) | ni1b;
            loc = umax64(loc, umax64(k0, k1));
        }

        // warp argmax via two redux ops
        {
            const uint32_t dbits = (uint32_t)(loc >> 21);
            const uint32_t wmax = redux_max(dbits);
            const uint32_t cand = (dbits == wmax) ? (uint32_t)(loc & 0x3FFFu) : 0u;
            const uint32_t nmax = redux_max(cand);
            if (lane == 0) s_part[wid] = ((u64)wmax << 21) | nmax;
        }
        __syncthreads();

        const int par = p & 1;
        if (wid == 0) {
            // stage 2: reduce the 32 CTA partials; publish + arrive on all ranks
            const u64 v = s_part[lane];
            const uint32_t dbits = (uint32_t)(v >> 21);
            const uint32_t wmax = redux_max(dbits);
            const uint32_t cand = (dbits == wmax) ? (uint32_t)(v & 0x3FFFu) : 0u;
            const uint32_t nmax = redux_max(cand);
            const u64 msg = ((u64)wmax << 21) | nmax;
            if (lane < CL) {
                st_cluster_u64(mb0 + (uint32_t)(par * CL + rank) * 8u, (uint32_t)lane, msg);
                mbar_arrive_remote(mbar_a, (uint32_t)lane);
            }
        }

        // sleep-wait for all 4 CTA partials (one arrive per rank), then plain LDS
        mbar_wait_parity(mbar_a, (uint32_t)par);
        const u64 v0 = mbox[par][0];
        const u64 v1 = mbox[par][1];
        const u64 v2 = mbox[par][2];
        const u64 v3 = mbox[par][3];
        const u64 g = umax64(umax64(v0, v1), umax64(v2, v3));
        f = 16383 - (int)(g & 0x3FFFu);
    }
    cluster_sync_all();  // no CTA exits while peers may still store into it
}

// ---------------------------------------------------------------------------
// Ball query: one warp per centroid, 256-thr blocks, no smem (high occupancy).
// Scan points in index order, append the first 32 within radius
// (strict d2 < 0.01f), pad with the first hit.
// ---------------------------------------------------------------------------
__global__ __launch_bounds__(256) void ball_kernel(const float* __restrict__ xyz,
                                                   const float* __restrict__ newxyz) {
    const int gw = (int)((blockIdx.x * blockDim.x + threadIdx.x) >> 5);
    const int lane = threadIdx.x & 31;
    if (gw >= BB * NPT) return;
    const int b = gw >> 10;

    const float* nx = newxyz + (size_t)gw * 3;
    const float cx = nx[0], cy = nx[1], cz = nx[2];
    const float* px = xyz + (size_t)b * NN * 3;
    int* out = g_nidx + (size_t)gw * NS;

    int count = 0;
    int first = 0;
    bool havefirst = false;

    for (int bs = 0; bs < NN; bs += 32) {
        const int i = bs + lane;
        const float dx = __fadd_rn(px[3 * i + 0], -cx);
        const float dy = __fadd_rn(px[3 * i + 1], -cy);
        const float dz = __fadd_rn(px[3 * i + 2], -cz);
        const float d2 =
            __fadd_rn(__fadd_rn(__fmul_rn(dx, dx), __fmul_rn(dy, dy)), __fmul_rn(dz, dz));
        const bool win = d2 < 0.01f;
        const unsigned m = __ballot_sync(0xffffffffu, win);
        if (m) {
            if (!havefirst) {
                first = bs + __ffs(m) - 1;
                havefirst = true;
            }
            const int slot = count + __popc(m & ((1u << lane) - 1u));
            if (win && slot < NS) out[slot] = i;
            count += __popc(m);
            if (count >= NS) break;
        }
    }
    if (lane >= count) out[lane] = first;  // pad (count<32 case); no-op if count>=32
}

// ---------------------------------------------------------------------------
// Gather + 3-layer MLP + max-pool. One warp per centroid, lane = sample.
// Spill-free: h1 staged in smem (per-thread column, stride 68 floats,
// STS/LDS.128, no cross-thread sharing so no barrier needed); h2 in regs.
// Weights in smem (LDS.128 broadcast). 8-wide accumulator ILP.
// ---------------------------------------------------------------------------
__global__ __launch_bounds__(128) void mlp_kernel(
    const float* __restrict__ xyz, const float* __restrict__ feat,
    const float* __restrict__ w1, const float* __restrict__ b1,
    const float* __restrict__ w2, const float* __restrict__ b2,
    const float* __restrict__ w3, const float* __restrict__ b3,
    const float* __restrict__ newxyz, float* __restrict__ outf) {
    extern __shared__ float sm[];
    float* sw1 = sm;                 // 64 x 68 (padded)
    float* sw2 = sw1 + 64 * 68;      // 64 x 64
    float* sw3 = sw2 + 64 * 64;      // 128 x 64
    float* sb1 = sw3 + 128 * 64;     // 64
    float* sb2 = sb1 + 64;           // 64
    float* sb3 = sb2 + 64;           // 128
    float* sh1 = sb3 + 128;          // 128 threads x 68 floats (h1 staging)

    const int tid = threadIdx.x;
    for (int i = tid; i < 64 * CIN; i += 128) sw1[(i / CIN) * 68 + (i % CIN)] = w1[i];
    for (int i = tid; i < 64 * 64; i += 128) sw2[i] = w2[i];
    for (int i = tid; i < 128 * 64; i += 128) sw3[i] = w3[i];
    if (tid < 64) {
        sb1[tid] = b1[tid];
        sb2[tid] = b2[tid];
    }
    if (tid < 128) sb3[tid] = b3[tid];
    __syncthreads();

    const int warp = tid >> 5, lane = tid & 31;
    const int pc = blockIdx.x * 4 + warp;  // global centroid id
    const int b = pc >> 10, p = pc & 1023;

    const int idx = g_nidx[pc * NS + lane];
    const float* P = xyz + ((size_t)b * NN + idx) * 3;
    const float* NXp = newxyz + (size_t)pc * 3;

    float in[CIN];
    in[0] = P[0] - NXp[0];
    in[1] = P[1] - NXp[1];
    in[2] = P[2] - NXp[2];
    const float4* F = (const float4*)(feat + ((size_t)b * NN + idx) * CF);
#pragma unroll
    for (int q = 0; q < 16; q++) {
        const float4 v = F[q];
        in[3 + 4 * q] = v.x;
        in[4 + 4 * q] = v.y;
        in[5 + 4 * q] = v.z;
        in[6 + 4 * q] = v.w;
    }

    float* myh1 = sh1 + tid * 68;  // 272B stride, 16B aligned

    // ---- layer 1: in[67] (regs) -> h1 (smem staging) ----
#pragma unroll 1
    for (int o = 0; o < 64; o += 8) {
        float acc[8];
#pragma unroll
        for (int j = 0; j < 8; j++) acc[j] = sb1[o + j];
#pragma unroll
        for (int c = 0; c < 64; c += 4) {
#pragma unroll
            for (int j = 0; j < 8; j++) {
                const float4 w = *(const float4*)&sw1[(o + j) * 68 + c];
                acc[j] = fmaf(in[c + 0], w.x, acc[j]);
                acc[j] = fmaf(in[c + 1], w.y, acc[j]);
                acc[j] = fmaf(in[c + 2], w.z, acc[j]);
                acc[j] = fmaf(in[c + 3], w.w, acc[j]);
            }
        }
#pragma unroll
        for (int j = 0; j < 8; j++) {
            acc[j] = fmaf(in[64], sw1[(o + j) * 68 + 64], acc[j]);
            acc[j] = fmaf(in[65], sw1[(o + j) * 68 + 65], acc[j]);
            acc[j] = fmaf(in[66], sw1[(o + j) * 68 + 66], acc[j]);
            acc[j] = fmaxf(acc[j], 0.0f);
        }
        *(float4*)&myh1[o + 0] = make_float4(acc[0], acc[1], acc[2], acc[3]);
        *(float4*)&myh1[o + 4] = make_float4(acc[4], acc[5], acc[6], acc[7]);
    }

    // ---- layer 2: h1 (smem) -> h2 (regs) ----
    float h2[64] __attribute__((aligned(16)));
#pragma unroll 1
    for (int o = 0; o < 64; o += 8) {
        float acc[8];
#pragma unroll
        for (int j = 0; j < 8; j++) acc[j] = sb2[o + j];
#pragma unroll
        for (int c = 0; c < 64; c += 4) {
            const float4 hv = *(const float4*)&myh1[c];
#pragma unroll
            for (int j = 0; j < 8; j++) {
                const float4 w = *(const float4*)&sw2[(o + j) * 64 + c];
                acc[j] = fmaf(hv.x, w.x, acc[j]);
                acc[j] = fmaf(hv.y, w.y, acc[j]);
                acc[j] = fmaf(hv.z, w.z, acc[j]);
                acc[j] = fmaf(hv.w, w.w, acc[j]);
            }
        }
#pragma unroll
        for (int j = 0; j < 8; j++) h2[o + j] = fmaxf(acc[j], 0.0f);
    }

    // ---- layer 3: h2 (regs) -> out, fused relu + sample max-pool ----
    const size_t obase = ((size_t)b * 128) * NPT + p;
#pragma unroll 1
    for (int o = 0; o < 128; o += 8) {
        float acc[8];
#pragma unroll
        for (int j = 0; j < 8; j++) acc[j] = sb3[o + j];
#pragma unroll
        for (int c = 0; c < 64; c += 4) {
            const float4 hv = *(const float4*)&h2[c];
#pragma unroll
            for (int j = 0; j < 8; j++) {
                const float4 w = *(const float4*)&sw3[(o + j) * 64 + c];
                acc[j] = fmaf(hv.x, w.x, acc[j]);
                acc[j] = fmaf(hv.y, w.y, acc[j]);
                acc[j] = fmaf(hv.z, w.z, acc[j]);
                acc[j] = fmaf(hv.w, w.w, acc[j]);
            }
        }
#pragma unroll
        for (int j = 0; j < 8; j++) {
            float v = fmaxf(acc[j], 0.0f);  // relu then max over samples
#pragma unroll
            for (int off = 16; off; off >>= 1)
                v = fmaxf(v, __shfl_xor_sync(0xffffffffu, v, off));
            if (lane == 0) outf[obase + (size_t)(o + j) * NPT] = v;
        }
    }
}

// ---------------------------------------------------------------------------
extern "C" void kernel_launch(void* const* d_in, const int* in_sizes, int n_in,
                              void* d_out, int out_size) {
    const float* xyz = (const float*)d_in[0];
    const float* feat = (const float*)d_in[1];
    const float* w1 = (const float*)d_in[2];
    const float* b1 = (const float*)d_in[3];
    const float* w2 = (const float*)d_in[4];
    const float* b2 = (const float*)d_in[5];
    const float* w3 = (const float*)d_in[6];
    const float* b3 = (const float*)d_in[7];

    float* out = (float*)d_out;
    float* newxyz = out;                  // (B, NPOINT, 3)
    float* outf = out + BB * NPT * 3;     // (B, 128, NPOINT)

    const int fps_smem = 8192 * 16 + 8192 * 8;  // 196608 B (full packed copy)
    const int mlp_smem =
        (64 * 68 + 64 * 64 + 128 * 64 + 64 + 64 + 128 + 128 * 68) * 4;  // 102400 B

    cudaFuncSetAttribute(fps_kernel, cudaFuncAttributeMaxDynamicSharedMemorySize, fps_smem);
    cudaFuncSetAttribute(mlp_kernel, cudaFuncAttributeMaxDynamicSharedMemorySize, mlp_smem);

    fps_kernel<<<BB * CL, 1024, fps_smem>>>(xyz, newxyz);
    ball_kernel<<<(BB * NPT * 32) / 256, 256>>>(xyz, newxyz);
    mlp_kernel<<<BB * NPT / 4, 128, mlp_smem>>>(xyz, feat, w1, b1, w2, b2, w3, b3, newxyz, outf);
}